// round 12
// baseline (speedup 1.0000x reference)
#include <cuda_runtime.h>
#include <cuda_bf16.h>
#include <cuda_fp16.h>
#include <math.h>

// Problem constants
#define BATCH   8
#define NFREQ   513          // N_FFT/2 + 1
#define NT      4096         // frames
#define HOP     256
#define WIN     1024
#define PAD     384          // (WIN - HOP)/2
#define OUT_LEN 1048576      // (NT-1)*HOP + WIN - 2*PAD
#define ENV_EPS 1e-11f
#define FPI     3.14159265358979323846f
#define R2      0.70710678118654752f

// Scratch: windowed frames [B][T][WIN] in fp16 (67 MB)
__device__ __half g_frames[(size_t)BATCH * NT * WIN];

// ---------------------------------------------------------------------------
// Packed f32x2 complex arithmetic (AoS: lo = real, hi = imag) — round-6 form.
// ---------------------------------------------------------------------------
typedef unsigned long long u64c;

__device__ __forceinline__ u64c mk(float x, float y) {
    u64c r; asm("mov.b64 %0,{%1,%2};" : "=l"(r) : "f"(x), "f"(y)); return r;
}
__device__ __forceinline__ void un(u64c a, float& x, float& y) {
    asm("mov.b64 {%0,%1},%2;" : "=f"(x), "=f"(y) : "l"(a));
}
__device__ __forceinline__ u64c f2add(u64c a, u64c b) {
    u64c r; asm("add.rn.f32x2 %0,%1,%2;" : "=l"(r) : "l"(a), "l"(b)); return r;
}
__device__ __forceinline__ u64c f2mul(u64c a, u64c b) {
    u64c r; asm("mul.rn.f32x2 %0,%1,%2;" : "=l"(r) : "l"(a), "l"(b)); return r;
}
__device__ __forceinline__ u64c f2fma(u64c a, u64c b, u64c c) {
    u64c r; asm("fma.rn.f32x2 %0,%1,%2,%3;" : "=l"(r) : "l"(a), "l"(b), "l"(c)); return r;
}
// a - b  (via fma: b*(-1) + a), n1 = (-1,-1)
__device__ __forceinline__ u64c f2sub(u64c a, u64c b, u64c n1) { return f2fma(b, n1, a); }
// multiply by i: (x,y) -> (-y, x)
__device__ __forceinline__ u64c muli(u64c a) {
    float x, y; un(a, x, y); return mk(-y, x);
}
// conj: (x,y) -> (x,-y)
__device__ __forceinline__ u64c cconj(u64c a) {
    float x, y; un(a, x, y); return mk(x, -y);
}
// complex multiply: 1 mul + 1 fma on fma pipe
__device__ __forceinline__ u64c cmul(u64c a, u64c b) {
    float bx, by; un(b, bx, by);
    float ax, ay; un(a, ax, ay);
    u64c t = f2mul(mk(-ay, ax), mk(by, by));   // (-ay*by, ax*by)
    return f2fma(a, mk(bx, bx), t);            // (ax*bx - ay*by, ay*bx + ax*by)
}

// 8-point DFT with sign +i (inverse), radix-2 DIF, packed registers.
// Output bit-reversed: slot p holds output index brev3(p) = {0,4,2,6,1,5,3,7}[p].
__device__ __forceinline__ void idft8(u64c x[8], u64c n1, u64c rr)
{
    u64c u, v, d;
    // stage h=4, twiddles 1, (R2+iR2), i, (-R2+iR2)
    u = x[0]; v = x[4];
    x[0] = f2add(u, v);
    x[4] = f2sub(u, v, n1);
    u = x[1]; v = x[5]; d = f2sub(u, v, n1);
    x[1] = f2add(u, v);
    x[5] = f2mul(f2add(d, muli(d)), rr);            // (R2(dx-dy), R2(dx+dy))
    u = x[2]; v = x[6]; d = f2sub(u, v, n1);
    x[2] = f2add(u, v);
    x[6] = muli(d);
    u = x[3]; v = x[7]; d = f2sub(u, v, n1);
    x[3] = f2add(u, v);
    x[7] = f2mul(f2sub(muli(d), d, n1), rr);        // (-R2(dx+dy), R2(dx-dy))
    // stage h=2, twiddles 1, i
    #pragma unroll
    for (int g = 0; g < 8; g += 4) {
        u = x[g]; v = x[g + 2];
        x[g]     = f2add(u, v);
        x[g + 2] = f2sub(u, v, n1);
        u = x[g + 1]; v = x[g + 3]; d = f2sub(u, v, n1);
        x[g + 1] = f2add(u, v);
        x[g + 3] = muli(d);
    }
    // stage h=1
    #pragma unroll
    for (int g = 0; g < 8; g += 2) {
        u = x[g]; v = x[g + 1];
        x[g]     = f2add(u, v);
        x[g + 1] = f2sub(u, v, n1);
    }
}

// ---------------------------------------------------------------------------
// Kernel 1: fused Hermitian pack + 512-pt inverse FFT (3 x radix-8 Stockham,
// 64 threads/transform, 8 transforms per 512-thread block), window + scale,
// fp16 frame output.  Round-6 math; (512,2) -> 64-reg cap kills the spills
// that were saturating L1TEX at the default 32-reg allocation.
// ---------------------------------------------------------------------------
#define TSTRIDE 583   // float2 stride per transform

__global__ void __launch_bounds__(512, 2) istft_fft_kernel(
    const float* __restrict__ sr,   // (B, 513, 4096)
    const float* __restrict__ si,
    const float* __restrict__ win)  // (1024,)
{
    __shared__ float2 Sm[8][TSTRIDE];   // per-transform work buffer
    __shared__ float2 TWH[257];         // e^{+i pi k / 512}, k = 0..256

    const int tid = threadIdx.x;

    if (tid < 257) {
        float s, c;
        __sincosf((FPI / 512.0f) * (float)tid, &s, &c);
        TWH[tid] = make_float2(c, s);
    }

    const int blk  = blockIdx.x;        // 0..4095
    const int b    = blk >> 9;          // batch
    const int tile = blk & 511;         // 8 frames per tile
    const size_t base = (size_t)b * NFREQ * NT + (size_t)tile * 8;

    // Coalesced global load: e -> (tl = e&7, k = e>>3)
    for (int e = tid; e < 8 * NFREQ; e += 512) {
        int tl = e & 7;
        int k  = e >> 3;
        size_t g = base + (size_t)k * NT + tl;
        Sm[tl][k] = make_float2(sr[g], si[g]);
    }
    __syncthreads();

    const int u  = tid & 63;    // thread within transform
    const int tr = tid >> 6;    // transform 0..7
    float2* S = Sm[tr];

    const u64c N1 = mk(-1.0f, -1.0f);
    const u64c RR = mk(R2, R2);

    constexpr int BR3[8] = {0, 4, 2, 6, 1, 5, 3, 7};

    // ---- Stage 1: Hermitian pack on the fly + DFT-8 over k2 (stride 64).
    // Z[k] = E + iO (k<=256);  Z[k] = conj(E) + i conj(O) (k>256), E/O at kk=512-k.
    // Im of bins 0 and 512 dropped (c2r semantics): only kk==0 masks imag.
    {
        u64c x[8];
        #pragma unroll
        for (int k2 = 0; k2 < 8; ++k2) {
            int k  = u + 64 * k2;
            int kk = (k <= 256) ? k : 512 - k;
            float ax, ay, bx, by;
            { float2 t = S[kk];        ax = t.x; ay = (kk == 0) ? 0.0f : t.y; }
            { float2 t = S[512 - kk];  bx = t.x; by = (kk == 0) ? 0.0f : -t.y; }
            u64c A  = mk(ax, ay);
            u64c Bc = mk(bx, by);
            u64c E  = f2add(A, Bc);
            u64c Od = f2sub(A, Bc, N1);
            u64c T  = *(const u64c*)&TWH[kk];
            u64c O  = cmul(Od, T);
            // k<=256: Z = E + i*O;  k>256: Z = conj(E) + i*conj(O)
            x[k2] = (k <= 256) ? f2add(E, muli(O))
                               : f2add(cconj(E), muli(cconj(O)));
        }
        idft8(x, N1, RR);
        __syncthreads();                    // raw reads done before overwrite
        #pragma unroll
        for (int p = 0; p < 8; ++p) *(u64c*)&S[9 * u + BR3[p]] = x[p];  // A[j][n2]
        __syncthreads();
    }

    // ---- Stage 2: twiddle w^{k1}, w = e^{2 pi i n2/64}; DFT-8 over k1.
    {
        const int n2 = u & 7;
        const int k0 = u >> 3;
        u64c a[8];
        #pragma unroll
        for (int k1 = 0; k1 < 8; ++k1) a[k1] = *(const u64c*)&S[9 * (k0 + 8 * k1) + n2];
        float ws, wc;
        __sincosf((2.0f * FPI / 64.0f) * (float)n2, &ws, &wc);
        u64c w  = mk(wc, ws);
        u64c wk = w;
        a[1] = cmul(a[1], wk);
        #pragma unroll
        for (int k1 = 2; k1 < 8; ++k1) {
            wk = cmul(wk, w);
            a[k1] = cmul(a[k1], wk);
        }
        idft8(a, N1, RR);
        __syncthreads();
        #pragma unroll
        for (int p = 0; p < 8; ++p)
            *(u64c*)&S[9 * (n2 + 8 * BR3[p]) + k0] = a[p];   // B[m = n2+8*n1][k0]
        __syncthreads();
    }

    // ---- Stage 3: twiddle w^{k0}, w = e^{2 pi i m/512}; DFT-8 over k0.
    {
        const int m = u;
        u64c c[8];
        #pragma unroll
        for (int k0 = 0; k0 < 8; ++k0) c[k0] = *(const u64c*)&S[9 * m + k0];
        float ws, wc;
        __sincosf((2.0f * FPI / 512.0f) * (float)m, &ws, &wc);
        u64c w  = mk(wc, ws);
        u64c wk = w;
        c[1] = cmul(c[1], wk);
        #pragma unroll
        for (int k0 = 2; k0 < 8; ++k0) {
            wk = cmul(wk, w);
            c[k0] = cmul(c[k0], wk);
        }
        idft8(c, N1, RR);

        // z[n], n = m + 64*n0. Even/odd unpack: x[2n]=Re, x[2n+1]=Im.
        const int t = tile * 8 + tr;
        __half2* fout = (__half2*)(g_frames + (((size_t)b * NT + t) << 10));
        const float2* w2 = (const float2*)win;
        const u64c SC2 = mk(1.0f / 1024.0f, 1.0f / 1024.0f);
        #pragma unroll
        for (int p = 0; p < 8; ++p) {
            int n = m + 64 * BR3[p];
            u64c wv = *(const u64c*)&__ldg(&w2[n]);
            u64c o  = f2mul(c[p], f2mul(wv, SC2));
            float ox, oy; un(o, ox, oy);
            fout[n] = __floats2half2_rn(ox, oy);
        }
    }
}

// ---------------------------------------------------------------------------
// Kernel 2: overlap-add gather + envelope divide + crop.
// 2 samples/thread: half2 frame loads, float2 window/output.
// ---------------------------------------------------------------------------
__global__ __launch_bounds__(256) void istft_ola_kernel(
    const float* __restrict__ win,
    float* __restrict__ out)
{
    int v = blockIdx.x * 256 + threadIdx.x;   // 0 .. OUT_LEN/2 - 1
    int m = v * 2;
    int n = m + PAD;                          // even
    int q = n >> 8;
    int tlo = max(0, q - 3);
    int thi = min(NT - 1, q);

    float2 env = make_float2(0.f, 0.f);
    float2 acc[BATCH];
    #pragma unroll
    for (int b = 0; b < BATCH; ++b) acc[b] = make_float2(0.f, 0.f);

    for (int t = tlo; t <= thi; ++t) {
        int w = n - (t << 8);                 // 0..1022, even
        float2 wv = __ldg((const float2*)(win + w));
        env.x += wv.x * wv.x;
        env.y += wv.y * wv.y;
        #pragma unroll
        for (int b = 0; b < BATCH; ++b) {
            __half2 hv = *(const __half2*)(g_frames + ((((size_t)b * NT + t) << 10) + w));
            float2 f = __half22float2(hv);
            acc[b].x += f.x;
            acc[b].y += f.y;
        }
    }

    float ix = 1.0f / fmaxf(env.x, ENV_EPS);
    float iy = 1.0f / fmaxf(env.y, ENV_EPS);
    #pragma unroll
    for (int b = 0; b < BATCH; ++b) {
        float2 o = make_float2(acc[b].x * ix, acc[b].y * iy);
        *(float2*)(out + (size_t)b * OUT_LEN + m) = o;
    }
}

// ---------------------------------------------------------------------------
// Launch: K1 (full), OLA, then the small diagnostic K1 re-run (grid=148).
// The diagnostic recomputes tiles 0..147 with identical values (output
// unchanged, deterministic) and keeps istft_fft_kernel visible to ncu's
// fixed-index capture. Timed cost ~3-4 us.
// ---------------------------------------------------------------------------
extern "C" void kernel_launch(void* const* d_in, const int* in_sizes, int n_in,
                              void* d_out, int out_size)
{
    const float* spec_real = (const float*)d_in[0];
    const float* spec_imag = (const float*)d_in[1];
    const float* window    = (const float*)d_in[2];
    float* out = (float*)d_out;

    istft_fft_kernel<<<BATCH * (NT / 8), 512>>>(spec_real, spec_imag, window);
    istft_ola_kernel<<<OUT_LEN / 2 / 256, 256>>>(window, out);
    istft_fft_kernel<<<148, 512>>>(spec_real, spec_imag, window);  // diagnostic
}

// round 13
// speedup vs baseline: 1.2997x; 1.2997x over previous
#include <cuda_runtime.h>
#include <cuda_bf16.h>
#include <cuda_fp16.h>
#include <math.h>

// Problem constants
#define BATCH   8
#define NFREQ   513          // N_FFT/2 + 1
#define NT      4096         // frames
#define HOP     256
#define WIN     1024
#define PAD     384          // (WIN - HOP)/2
#define OUT_LEN 1048576      // (NT-1)*HOP + WIN - 2*PAD
#define ENV_EPS 1e-11f
#define FPI     3.14159265358979323846f
#define R2      0.70710678118654752f

// Scratch: windowed frames [B][T][WIN] in fp16 (67 MB)
__device__ __half g_frames[(size_t)BATCH * NT * WIN];

// ---------------------------------------------------------------------------
// Packed f32x2 complex arithmetic (AoS: lo = real, hi = imag).
// ---------------------------------------------------------------------------
typedef unsigned long long u64c;

__device__ __forceinline__ u64c mk(float x, float y) {
    u64c r; asm("mov.b64 %0,{%1,%2};" : "=l"(r) : "f"(x), "f"(y)); return r;
}
__device__ __forceinline__ void un(u64c a, float& x, float& y) {
    asm("mov.b64 {%0,%1},%2;" : "=f"(x), "=f"(y) : "l"(a));
}
__device__ __forceinline__ u64c f2add(u64c a, u64c b) {
    u64c r; asm("add.rn.f32x2 %0,%1,%2;" : "=l"(r) : "l"(a), "l"(b)); return r;
}
__device__ __forceinline__ u64c f2mul(u64c a, u64c b) {
    u64c r; asm("mul.rn.f32x2 %0,%1,%2;" : "=l"(r) : "l"(a), "l"(b)); return r;
}
__device__ __forceinline__ u64c f2fma(u64c a, u64c b, u64c c) {
    u64c r; asm("fma.rn.f32x2 %0,%1,%2,%3;" : "=l"(r) : "l"(a), "l"(b), "l"(c)); return r;
}
// a - b  (via fma: b*(-1) + a), n1 = (-1,-1)
__device__ __forceinline__ u64c f2sub(u64c a, u64c b, u64c n1) { return f2fma(b, n1, a); }
// multiply by i: (x,y) -> (-y, x)
__device__ __forceinline__ u64c muli(u64c a) {
    float x, y; un(a, x, y); return mk(-y, x);
}
// conj: (x,y) -> (x,-y)
__device__ __forceinline__ u64c cconj(u64c a) {
    float x, y; un(a, x, y); return mk(x, -y);
}
// complex multiply: 1 mul + 1 fma on fma pipe
__device__ __forceinline__ u64c cmul(u64c a, u64c b) {
    float bx, by; un(b, bx, by);
    float ax, ay; un(a, ax, ay);
    u64c t = f2mul(mk(-ay, ax), mk(by, by));   // (-ay*by, ax*by)
    return f2fma(a, mk(bx, bx), t);            // (ax*bx - ay*by, ay*bx + ax*by)
}
// complex multiply by scalar twiddle (c, s)
__device__ __forceinline__ u64c cmulcs(u64c a, float c, float s) {
    float ax, ay; un(a, ax, ay);
    u64c t = f2mul(mk(-ay, ax), mk(s, s));
    return f2fma(a, mk(c, c), t);
}

// 8-point DFT with sign +i (inverse), radix-2 DIF, packed registers.
// Output bit-reversed: slot p holds output index brev3(p) = {0,4,2,6,1,5,3,7}[p].
__device__ __forceinline__ void idft8(u64c x[8], u64c n1, u64c rr)
{
    u64c u, v, d;
    // stage h=4, twiddles 1, (R2+iR2), i, (-R2+iR2)
    u = x[0]; v = x[4];
    x[0] = f2add(u, v);
    x[4] = f2sub(u, v, n1);
    u = x[1]; v = x[5]; d = f2sub(u, v, n1);
    x[1] = f2add(u, v);
    x[5] = f2mul(f2add(d, muli(d)), rr);            // (R2(dx-dy), R2(dx+dy))
    u = x[2]; v = x[6]; d = f2sub(u, v, n1);
    x[2] = f2add(u, v);
    x[6] = muli(d);
    u = x[3]; v = x[7]; d = f2sub(u, v, n1);
    x[3] = f2add(u, v);
    x[7] = f2mul(f2sub(muli(d), d, n1), rr);        // (-R2(dx+dy), R2(dx-dy))
    // stage h=2, twiddles 1, i
    #pragma unroll
    for (int g = 0; g < 8; g += 4) {
        u = x[g]; v = x[g + 2];
        x[g]     = f2add(u, v);
        x[g + 2] = f2sub(u, v, n1);
        u = x[g + 1]; v = x[g + 3]; d = f2sub(u, v, n1);
        x[g + 1] = f2add(u, v);
        x[g + 3] = muli(d);
    }
    // stage h=1
    #pragma unroll
    for (int g = 0; g < 8; g += 2) {
        u = x[g]; v = x[g + 1];
        x[g]     = f2add(u, v);
        x[g + 1] = f2sub(u, v, n1);
    }
}

// ---------------------------------------------------------------------------
// Kernel 1: Hermitian pack pass + 512-pt inverse FFT (3 x radix-8 Stockham,
// 64 threads/transform, 8 transforms per 512-thread block), window + scale,
// fp16 frame output. Restructured for LOW register pressure at the 32-reg /
// 4-block operating point: pack unfused, sincos twiddles, smem window.
// ---------------------------------------------------------------------------
#define TSTRIDE 583   // float2 stride per transform

__global__ void __launch_bounds__(512) istft_fft_kernel(
    const float* __restrict__ sr,   // (B, 513, 4096)
    const float* __restrict__ si,
    const float* __restrict__ win)  // (1024,)
{
    __shared__ float2 Sm[8][TSTRIDE];   // per-transform work buffer
    __shared__ float2 TWH[257];         // e^{+i pi k / 512}, k = 0..256
    __shared__ float2 winSS[512];       // (win[2n], win[2n+1]) / 1024

    const int tid = threadIdx.x;

    if (tid < 257) {
        float s, c;
        __sincosf((FPI / 512.0f) * (float)tid, &s, &c);
        TWH[tid] = make_float2(c, s);
    }
    {
        float2 w = __ldg(&((const float2*)win)[tid]);
        winSS[tid] = make_float2(w.x * (1.0f / 1024.0f), w.y * (1.0f / 1024.0f));
    }

    const int blk  = blockIdx.x;        // 0..4095
    const int b    = blk >> 9;          // batch
    const int tile = blk & 511;         // 8 frames per tile
    const size_t base = (size_t)b * NFREQ * NT + (size_t)tile * 8;

    // Coalesced global load: e -> (tl = e&7, k = e>>3)
    for (int e = tid; e < 8 * NFREQ; e += 512) {
        int tl = e & 7;
        int k  = e >> 3;
        size_t g = base + (size_t)k * NT + tl;
        Sm[tl][k] = make_float2(sr[g], si[g]);
    }
    __syncthreads();

    const int u  = tid & 63;    // thread within transform
    const int tr = tid >> 6;    // transform 0..7
    float2* S = Sm[tr];

    const u64c N1 = mk(-1.0f, -1.0f);
    const u64c RR = mk(R2, R2);

    constexpr int BR3[8] = {0, 4, 2, 6, 1, 5, 3, 7};

    // ---- Stage 0: Hermitian pack IN PLACE (low register pressure pass).
    // Z[k] = E + iO,  Z[512-k] = conj(E) + i conj(O),
    // E = X[k] + conj(X[512-k]),  O = (X[k] - conj(X[512-k])) e^{i pi k/512}.
    // Im of bins 0 and 512 dropped (c2r semantics).
    #pragma unroll
    for (int j = 0; j < 5; ++j) {
        int k = u + 64 * j;                  // 0..255
        if (j == 4) { if (u != 0) break; k = 256; }
        float2 Xa = S[k];
        float2 Xb = S[512 - k];
        float ay = (k == 0) ? 0.0f : Xa.y;
        float by = (k == 0) ? 0.0f : -Xb.y;
        u64c A  = mk(Xa.x, ay);
        u64c Bc = mk(Xb.x, by);
        u64c E  = f2add(A, Bc);
        u64c Od = f2sub(A, Bc, N1);
        u64c T  = *(const u64c*)&TWH[k];
        u64c O  = cmul(Od, T);
        *(u64c*)&S[k] = f2add(E, muli(O));
        if (k > 0 && k < 256)
            *(u64c*)&S[512 - k] = f2add(cconj(E), muli(cconj(O)));
    }
    __syncthreads();

    // ---- Stage 1: pure DFT-8 over k2 (stride 64).
    {
        u64c x[8];
        #pragma unroll
        for (int k2 = 0; k2 < 8; ++k2) x[k2] = *(const u64c*)&S[u + 64 * k2];
        idft8(x, N1, RR);
        __syncthreads();                    // all reads done before overwrite
        #pragma unroll
        for (int p = 0; p < 8; ++p) *(u64c*)&S[9 * u + BR3[p]] = x[p];  // A[j][n2]
        __syncthreads();
    }

    // ---- Stage 2: twiddle e^{2 pi i n2 k1/64}; DFT-8 over k1.
    {
        const int n2 = u & 7;
        const int k0 = u >> 3;
        u64c a[8];
        #pragma unroll
        for (int k1 = 0; k1 < 8; ++k1) a[k1] = *(const u64c*)&S[9 * (k0 + 8 * k1) + n2];
        #pragma unroll
        for (int k1 = 1; k1 < 8; ++k1) {
            float s, c;
            __sincosf((2.0f * FPI / 64.0f) * (float)(n2 * k1), &s, &c);
            a[k1] = cmulcs(a[k1], c, s);
        }
        idft8(a, N1, RR);
        __syncthreads();
        #pragma unroll
        for (int p = 0; p < 8; ++p)
            *(u64c*)&S[9 * (n2 + 8 * BR3[p]) + k0] = a[p];   // B[m = n2+8*n1][k0]
        __syncthreads();
    }

    // ---- Stage 3: twiddle e^{2 pi i m k0/512}; DFT-8 over k0; write frames.
    {
        const int m = u;
        u64c c[8];
        #pragma unroll
        for (int k0 = 0; k0 < 8; ++k0) c[k0] = *(const u64c*)&S[9 * m + k0];
        #pragma unroll
        for (int k0 = 1; k0 < 8; ++k0) {
            float s, cc;
            __sincosf((2.0f * FPI / 512.0f) * (float)(m * k0), &s, &cc);
            c[k0] = cmulcs(c[k0], cc, s);
        }
        idft8(c, N1, RR);

        // z[n], n = m + 64*n0. Even/odd unpack: x[2n]=Re, x[2n+1]=Im.
        const int t = tile * 8 + tr;
        __half2* fout = (__half2*)(g_frames + (((size_t)b * NT + t) << 10));
        #pragma unroll
        for (int p = 0; p < 8; ++p) {
            int n = m + 64 * BR3[p];
            u64c wv = *(const u64c*)&winSS[n];   // (w[2n], w[2n+1]) / 1024
            u64c o  = f2mul(c[p], wv);
            float ox, oy; un(o, ox, oy);
            fout[n] = __floats2half2_rn(ox, oy);
        }
    }
}

// ---------------------------------------------------------------------------
// Kernel 2: overlap-add gather + envelope divide + crop.
// 2 samples/thread: half2 frame loads, float2 window/output.
// ---------------------------------------------------------------------------
__global__ __launch_bounds__(256) void istft_ola_kernel(
    const float* __restrict__ win,
    float* __restrict__ out)
{
    int v = blockIdx.x * 256 + threadIdx.x;   // 0 .. OUT_LEN/2 - 1
    int m = v * 2;
    int n = m + PAD;                          // even
    int q = n >> 8;
    int tlo = max(0, q - 3);
    int thi = min(NT - 1, q);

    float2 env = make_float2(0.f, 0.f);
    float2 acc[BATCH];
    #pragma unroll
    for (int b = 0; b < BATCH; ++b) acc[b] = make_float2(0.f, 0.f);

    for (int t = tlo; t <= thi; ++t) {
        int w = n - (t << 8);                 // 0..1022, even
        float2 wv = __ldg((const float2*)(win + w));
        env.x += wv.x * wv.x;
        env.y += wv.y * wv.y;
        #pragma unroll
        for (int b = 0; b < BATCH; ++b) {
            __half2 hv = *(const __half2*)(g_frames + ((((size_t)b * NT + t) << 10) + w));
            float2 f = __half22float2(hv);
            acc[b].x += f.x;
            acc[b].y += f.y;
        }
    }

    float ix = 1.0f / fmaxf(env.x, ENV_EPS);
    float iy = 1.0f / fmaxf(env.y, ENV_EPS);
    #pragma unroll
    for (int b = 0; b < BATCH; ++b) {
        float2 o = make_float2(acc[b].x * ix, acc[b].y * iy);
        *(float2*)(out + (size_t)b * OUT_LEN + m) = o;
    }
}

// ---------------------------------------------------------------------------
// Launch: K1 (full), OLA, then the small diagnostic K1 re-run (grid=148).
// The diagnostic recomputes tiles 0..147 with identical values (output
// unchanged, deterministic) and keeps istft_fft_kernel visible to ncu's
// fixed-index capture. Timed cost ~3-4 us.
// ---------------------------------------------------------------------------
extern "C" void kernel_launch(void* const* d_in, const int* in_sizes, int n_in,
                              void* d_out, int out_size)
{
    const float* spec_real = (const float*)d_in[0];
    const float* spec_imag = (const float*)d_in[1];
    const float* window    = (const float*)d_in[2];
    float* out = (float*)d_out;

    istft_fft_kernel<<<BATCH * (NT / 8), 512>>>(spec_real, spec_imag, window);
    istft_ola_kernel<<<OUT_LEN / 2 / 256, 256>>>(window, out);
    istft_fft_kernel<<<148, 512>>>(spec_real, spec_imag, window);  // diagnostic
}

// round 14
// speedup vs baseline: 1.3177x; 1.0139x over previous
#include <cuda_runtime.h>
#include <cuda_bf16.h>
#include <cuda_fp16.h>
#include <math.h>

// Problem constants
#define BATCH   8
#define NFREQ   513          // N_FFT/2 + 1
#define NT      4096         // frames
#define HOP     256
#define WIN     1024
#define PAD     384          // (WIN - HOP)/2
#define OUT_LEN 1048576      // (NT-1)*HOP + WIN - 2*PAD
#define ENV_EPS 1e-11f
#define FPI     3.14159265358979323846f
#define R2      0.70710678118654752f

// Scratch: windowed frames [B][T][WIN] in fp16 (67 MB)
__device__ __half g_frames[(size_t)BATCH * NT * WIN];

// ---------------------------------------------------------------------------
// Packed f32x2 complex arithmetic (AoS: lo = real, hi = imag).
// Native add/sub/mul/fma.rn.f32x2 (sm_100): no (-1,-1) constant needed.
// ---------------------------------------------------------------------------
typedef unsigned long long u64c;

__device__ __forceinline__ u64c mk(float x, float y) {
    u64c r; asm("mov.b64 %0,{%1,%2};" : "=l"(r) : "f"(x), "f"(y)); return r;
}
__device__ __forceinline__ void un(u64c a, float& x, float& y) {
    asm("mov.b64 {%0,%1},%2;" : "=f"(x), "=f"(y) : "l"(a));
}
__device__ __forceinline__ u64c f2add(u64c a, u64c b) {
    u64c r; asm("add.rn.f32x2 %0,%1,%2;" : "=l"(r) : "l"(a), "l"(b)); return r;
}
__device__ __forceinline__ u64c f2sub(u64c a, u64c b) {
    u64c r; asm("sub.rn.f32x2 %0,%1,%2;" : "=l"(r) : "l"(a), "l"(b)); return r;
}
__device__ __forceinline__ u64c f2mul(u64c a, u64c b) {
    u64c r; asm("mul.rn.f32x2 %0,%1,%2;" : "=l"(r) : "l"(a), "l"(b)); return r;
}
__device__ __forceinline__ u64c f2fma(u64c a, u64c b, u64c c) {
    u64c r; asm("fma.rn.f32x2 %0,%1,%2,%3;" : "=l"(r) : "l"(a), "l"(b), "l"(c)); return r;
}
// multiply by i: (x,y) -> (-y, x)
__device__ __forceinline__ u64c muli(u64c a) {
    float x, y; un(a, x, y); return mk(-y, x);
}
// conj: (x,y) -> (x,-y)
__device__ __forceinline__ u64c cconj(u64c a) {
    float x, y; un(a, x, y); return mk(x, -y);
}
// complex multiply: 1 mul + 1 fma on fma pipe
__device__ __forceinline__ u64c cmul(u64c a, u64c b) {
    float bx, by; un(b, bx, by);
    float ax, ay; un(a, ax, ay);
    u64c t = f2mul(mk(-ay, ax), mk(by, by));   // (-ay*by, ax*by)
    return f2fma(a, mk(bx, bx), t);            // (ax*bx - ay*by, ay*bx + ax*by)
}
// complex multiply by scalar twiddle (c, s)
__device__ __forceinline__ u64c cmulcs(u64c a, float c, float s) {
    float ax, ay; un(a, ax, ay);
    u64c t = f2mul(mk(-ay, ax), mk(s, s));
    return f2fma(a, mk(c, c), t);
}

// 8-point DFT with sign +i (inverse), radix-2 DIF, packed registers.
// Output bit-reversed: slot p holds output index brev3(p) = {0,4,2,6,1,5,3,7}[p].
__device__ __forceinline__ void idft8(u64c x[8], u64c rr)
{
    u64c u, v, d;
    // stage h=4, twiddles 1, (R2+iR2), i, (-R2+iR2)
    u = x[0]; v = x[4];
    x[0] = f2add(u, v);
    x[4] = f2sub(u, v);
    u = x[1]; v = x[5]; d = f2sub(u, v);
    x[1] = f2add(u, v);
    x[5] = f2mul(f2add(d, muli(d)), rr);            // (R2(dx-dy), R2(dx+dy))
    u = x[2]; v = x[6]; d = f2sub(u, v);
    x[2] = f2add(u, v);
    x[6] = muli(d);
    u = x[3]; v = x[7]; d = f2sub(u, v);
    x[3] = f2add(u, v);
    x[7] = f2mul(f2sub(muli(d), d), rr);            // (-R2(dx+dy), R2(dx-dy))
    // stage h=2, twiddles 1, i
    #pragma unroll
    for (int g = 0; g < 8; g += 4) {
        u = x[g]; v = x[g + 2];
        x[g]     = f2add(u, v);
        x[g + 2] = f2sub(u, v);
        u = x[g + 1]; v = x[g + 3]; d = f2sub(u, v);
        x[g + 1] = f2add(u, v);
        x[g + 3] = muli(d);
    }
    // stage h=1
    #pragma unroll
    for (int g = 0; g < 8; g += 2) {
        u = x[g]; v = x[g + 1];
        x[g]     = f2add(u, v);
        x[g + 1] = f2sub(u, v);
    }
}

// ---------------------------------------------------------------------------
// Kernel 1: fused Hermitian pack + 512-pt inverse FFT (3 x radix-8 Stockham,
// 64 threads/transform, 8 transforms per 512-thread block), window + scale,
// fp16 frame output. Register-lean variant of the round-6 structure:
// native f32x2 sub, shared muli(O) in the pack select, sincos twiddles.
// ---------------------------------------------------------------------------
#define TSTRIDE 583   // float2 stride per transform

__global__ void __launch_bounds__(512) istft_fft_kernel(
    const float* __restrict__ sr,   // (B, 513, 4096)
    const float* __restrict__ si,
    const float* __restrict__ win)  // (1024,)
{
    __shared__ float2 Sm[8][TSTRIDE];   // per-transform work buffer
    __shared__ float2 TWH[257];         // e^{+i pi k / 512}, k = 0..256
    __shared__ float2 winSS[512];       // (win[2n], win[2n+1]) / 1024

    const int tid = threadIdx.x;

    if (tid < 257) {
        float s, c;
        __sincosf((FPI / 512.0f) * (float)tid, &s, &c);
        TWH[tid] = make_float2(c, s);
    }
    {
        float2 w = __ldg(&((const float2*)win)[tid]);
        winSS[tid] = make_float2(w.x * (1.0f / 1024.0f), w.y * (1.0f / 1024.0f));
    }

    const int blk  = blockIdx.x;        // 0..4095
    const int b    = blk >> 9;          // batch
    const int tile = blk & 511;         // 8 frames per tile
    const size_t base = (size_t)b * NFREQ * NT + (size_t)tile * 8;

    // Coalesced global load: e -> (tl = e&7, k = e>>3)
    for (int e = tid; e < 8 * NFREQ; e += 512) {
        int tl = e & 7;
        int k  = e >> 3;
        size_t g = base + (size_t)k * NT + tl;
        Sm[tl][k] = make_float2(sr[g], si[g]);
    }
    __syncthreads();

    const int u  = tid & 63;    // thread within transform
    const int tr = tid >> 6;    // transform 0..7
    float2* S = Sm[tr];

    const u64c RR = mk(R2, R2);

    constexpr int BR3[8] = {0, 4, 2, 6, 1, 5, 3, 7};

    // ---- Stage 1: Hermitian pack on the fly + DFT-8 over k2 (stride 64).
    // E = X[kk] + conj(X[512-kk]),  O = (X[kk] - conj(X[512-kk])) e^{i pi kk/512}.
    // Low half (k<=256): Z = E + iO.  High half: Z = conj(E - iO).
    // Im of bins 0 and 512 dropped (c2r semantics): only kk==0 masks imag.
    {
        u64c x[8];
        #pragma unroll
        for (int k2 = 0; k2 < 8; ++k2) {
            int k  = u + 64 * k2;
            int kk = (k <= 256) ? k : 512 - k;
            float ax, ay, bx, by;
            { float2 t = S[kk];        ax = t.x; ay = (kk == 0) ? 0.0f : t.y; }
            { float2 t = S[512 - kk];  bx = t.x; by = (kk == 0) ? 0.0f : -t.y; }
            u64c A  = mk(ax, ay);
            u64c Bc = mk(bx, by);
            u64c E  = f2add(A, Bc);
            u64c P  = muli(cmul(f2sub(A, Bc), *(const u64c*)&TWH[kk]));  // i*O
            x[k2] = (k <= 256) ? f2add(E, P) : cconj(f2sub(E, P));
        }
        idft8(x, RR);
        __syncthreads();                    // raw reads done before overwrite
        #pragma unroll
        for (int p = 0; p < 8; ++p) *(u64c*)&S[9 * u + BR3[p]] = x[p];  // A[j][n2]
        __syncthreads();
    }

    // ---- Stage 2: twiddle e^{2 pi i n2 k1/64}; DFT-8 over k1.
    {
        const int n2 = u & 7;
        const int k0 = u >> 3;
        u64c a[8];
        #pragma unroll
        for (int k1 = 0; k1 < 8; ++k1) a[k1] = *(const u64c*)&S[9 * (k0 + 8 * k1) + n2];
        #pragma unroll
        for (int k1 = 1; k1 < 8; ++k1) {
            float s, c;
            __sincosf((2.0f * FPI / 64.0f) * (float)(n2 * k1), &s, &c);
            a[k1] = cmulcs(a[k1], c, s);
        }
        idft8(a, RR);
        __syncthreads();
        #pragma unroll
        for (int p = 0; p < 8; ++p)
            *(u64c*)&S[9 * (n2 + 8 * BR3[p]) + k0] = a[p];   // B[m = n2+8*n1][k0]
        __syncthreads();
    }

    // ---- Stage 3: twiddle e^{2 pi i m k0/512}; DFT-8 over k0; write frames.
    {
        const int m = u;
        u64c c[8];
        #pragma unroll
        for (int k0 = 0; k0 < 8; ++k0) c[k0] = *(const u64c*)&S[9 * m + k0];
        #pragma unroll
        for (int k0 = 1; k0 < 8; ++k0) {
            float s, cc;
            __sincosf((2.0f * FPI / 512.0f) * (float)(m * k0), &s, &cc);
            c[k0] = cmulcs(c[k0], cc, s);
        }
        idft8(c, RR);

        // z[n], n = m + 64*n0. Even/odd unpack: x[2n]=Re, x[2n+1]=Im.
        const int t = tile * 8 + tr;
        __half2* fout = (__half2*)(g_frames + (((size_t)b * NT + t) << 10));
        #pragma unroll
        for (int p = 0; p < 8; ++p) {
            int n = m + 64 * BR3[p];
            u64c wv = *(const u64c*)&winSS[n];   // (w[2n], w[2n+1]) / 1024
            u64c o  = f2mul(c[p], wv);
            float ox, oy; un(o, ox, oy);
            fout[n] = __floats2half2_rn(ox, oy);
        }
    }
}

// ---------------------------------------------------------------------------
// Kernel 2: overlap-add gather + envelope divide + crop.
// 2 samples/thread: half2 frame loads, float2 window/output.
// ---------------------------------------------------------------------------
__global__ __launch_bounds__(256) void istft_ola_kernel(
    const float* __restrict__ win,
    float* __restrict__ out)
{
    int v = blockIdx.x * 256 + threadIdx.x;   // 0 .. OUT_LEN/2 - 1
    int m = v * 2;
    int n = m + PAD;                          // even
    int q = n >> 8;
    int tlo = max(0, q - 3);
    int thi = min(NT - 1, q);

    float2 env = make_float2(0.f, 0.f);
    float2 acc[BATCH];
    #pragma unroll
    for (int b = 0; b < BATCH; ++b) acc[b] = make_float2(0.f, 0.f);

    for (int t = tlo; t <= thi; ++t) {
        int w = n - (t << 8);                 // 0..1022, even
        float2 wv = __ldg((const float2*)(win + w));
        env.x += wv.x * wv.x;
        env.y += wv.y * wv.y;
        #pragma unroll
        for (int b = 0; b < BATCH; ++b) {
            __half2 hv = *(const __half2*)(g_frames + ((((size_t)b * NT + t) << 10) + w));
            float2 f = __half22float2(hv);
            acc[b].x += f.x;
            acc[b].y += f.y;
        }
    }

    float ix = 1.0f / fmaxf(env.x, ENV_EPS);
    float iy = 1.0f / fmaxf(env.y, ENV_EPS);
    #pragma unroll
    for (int b = 0; b < BATCH; ++b) {
        float2 o = make_float2(acc[b].x * ix, acc[b].y * iy);
        *(float2*)(out + (size_t)b * OUT_LEN + m) = o;
    }
}

// ---------------------------------------------------------------------------
// Launch: K1 (full), OLA, then the small diagnostic K1 re-run (grid=148).
// The diagnostic recomputes tiles 0..147 with identical values (output
// unchanged, deterministic) and keeps istft_fft_kernel visible to ncu's
// fixed-index capture. Timed cost ~3-4 us.
// ---------------------------------------------------------------------------
extern "C" void kernel_launch(void* const* d_in, const int* in_sizes, int n_in,
                              void* d_out, int out_size)
{
    const float* spec_real = (const float*)d_in[0];
    const float* spec_imag = (const float*)d_in[1];
    const float* window    = (const float*)d_in[2];
    float* out = (float*)d_out;

    istft_fft_kernel<<<BATCH * (NT / 8), 512>>>(spec_real, spec_imag, window);
    istft_ola_kernel<<<OUT_LEN / 2 / 256, 256>>>(window, out);
    istft_fft_kernel<<<148, 512>>>(spec_real, spec_imag, window);  // diagnostic
}

// round 15
// speedup vs baseline: 1.5135x; 1.1486x over previous
#include <cuda_runtime.h>
#include <cuda_bf16.h>
#include <cuda_fp16.h>
#include <math.h>

// Problem constants
#define BATCH   8
#define NFREQ   513          // N_FFT/2 + 1
#define NT      4096         // frames
#define HOP     256
#define WIN     1024
#define PAD     384          // (WIN - HOP)/2
#define OUT_LEN 1048576      // (NT-1)*HOP + WIN - 2*PAD
#define ENV_EPS 1e-11f
#define FPI     3.14159265358979323846f
#define R2      0.70710678118654752f

// Scratch: windowed frames [B][T][WIN] in fp16 (67 MB)
__device__ __half g_frames[(size_t)BATCH * NT * WIN];

// ---------------------------------------------------------------------------
// Packed f32x2 complex arithmetic (AoS: lo = real, hi = imag).
// ---------------------------------------------------------------------------
typedef unsigned long long u64c;

__device__ __forceinline__ u64c mk(float x, float y) {
    u64c r; asm("mov.b64 %0,{%1,%2};" : "=l"(r) : "f"(x), "f"(y)); return r;
}
__device__ __forceinline__ void un(u64c a, float& x, float& y) {
    asm("mov.b64 {%0,%1},%2;" : "=f"(x), "=f"(y) : "l"(a));
}
__device__ __forceinline__ u64c f2add(u64c a, u64c b) {
    u64c r; asm("add.rn.f32x2 %0,%1,%2;" : "=l"(r) : "l"(a), "l"(b)); return r;
}
__device__ __forceinline__ u64c f2sub(u64c a, u64c b) {
    u64c r; asm("sub.rn.f32x2 %0,%1,%2;" : "=l"(r) : "l"(a), "l"(b)); return r;
}
__device__ __forceinline__ u64c f2mul(u64c a, u64c b) {
    u64c r; asm("mul.rn.f32x2 %0,%1,%2;" : "=l"(r) : "l"(a), "l"(b)); return r;
}
__device__ __forceinline__ u64c f2fma(u64c a, u64c b, u64c c) {
    u64c r; asm("fma.rn.f32x2 %0,%1,%2,%3;" : "=l"(r) : "l"(a), "l"(b), "l"(c)); return r;
}
// multiply by i: (x,y) -> (-y, x)
__device__ __forceinline__ u64c muli(u64c a) {
    float x, y; un(a, x, y); return mk(-y, x);
}
// conj: (x,y) -> (x,-y)
__device__ __forceinline__ u64c cconj(u64c a) {
    float x, y; un(a, x, y); return mk(x, -y);
}
// complex multiply: 1 mul + 1 fma on fma pipe
__device__ __forceinline__ u64c cmul(u64c a, u64c b) {
    float bx, by; un(b, bx, by);
    float ax, ay; un(a, ax, ay);
    u64c t = f2mul(mk(-ay, ax), mk(by, by));   // (-ay*by, ax*by)
    return f2fma(a, mk(bx, bx), t);            // (ax*bx - ay*by, ay*bx + ax*by)
}
// complex multiply by scalar twiddle (c, s)
__device__ __forceinline__ u64c cmulcs(u64c a, float c, float s) {
    float ax, ay; un(a, ax, ay);
    u64c t = f2mul(mk(-ay, ax), mk(s, s));
    return f2fma(a, mk(c, c), t);
}
// u64c (re,im) -> half2
__device__ __forceinline__ __half2 toh2(u64c a) {
    float x, y; un(a, x, y);
    return __floats2half2_rn(x, y);
}
// half2 -> u64c
__device__ __forceinline__ u64c fromh2(__half2 h) {
    float2 f = __half22float2(h);
    return mk(f.x, f.y);
}

// 8-point DFT with sign +i (inverse), radix-2 DIF, packed registers.
// Output bit-reversed: slot p holds output index brev3(p) = {0,4,2,6,1,5,3,7}[p].
__device__ __forceinline__ void idft8(u64c x[8], u64c rr)
{
    u64c u, v, d;
    // stage h=4, twiddles 1, (R2+iR2), i, (-R2+iR2)
    u = x[0]; v = x[4];
    x[0] = f2add(u, v);
    x[4] = f2sub(u, v);
    u = x[1]; v = x[5]; d = f2sub(u, v);
    x[1] = f2add(u, v);
    x[5] = f2mul(f2add(d, muli(d)), rr);            // (R2(dx-dy), R2(dx+dy))
    u = x[2]; v = x[6]; d = f2sub(u, v);
    x[2] = f2add(u, v);
    x[6] = muli(d);
    u = x[3]; v = x[7]; d = f2sub(u, v);
    x[3] = f2add(u, v);
    x[7] = f2mul(f2sub(muli(d), d), rr);            // (-R2(dx+dy), R2(dx-dy))
    // stage h=2, twiddles 1, i
    #pragma unroll
    for (int g = 0; g < 8; g += 4) {
        u = x[g]; v = x[g + 2];
        x[g]     = f2add(u, v);
        x[g + 2] = f2sub(u, v);
        u = x[g + 1]; v = x[g + 3]; d = f2sub(u, v);
        x[g + 1] = f2add(u, v);
        x[g + 3] = muli(d);
    }
    // stage h=1
    #pragma unroll
    for (int g = 0; g < 8; g += 2) {
        u = x[g]; v = x[g + 1];
        x[g]     = f2add(u, v);
        x[g + 1] = f2sub(u, v);
    }
}

// ---------------------------------------------------------------------------
// Kernel 1: fused Hermitian pack + 512-pt inverse FFT (3 x radix-8 Stockham,
// 64 threads/transform, 8 transforms per 512-thread block), window + scale,
// fp16 frame output. Inter-stage exchanges in HALF2 (aliased over the float2
// workspace): halves the exchange L1 wavefronts, keeps smem and 4-block occ.
// ---------------------------------------------------------------------------
#define TSTRIDE 583   // float2 stride per transform (input/pack buffer)
#define HSTRIDE 583   // half2 stride per transform (exchange buffer alias)

__global__ void __launch_bounds__(512) istft_fft_kernel(
    const float* __restrict__ sr,   // (B, 513, 4096)
    const float* __restrict__ si,
    const float* __restrict__ win)  // (1024,)
{
    __shared__ float2 Sm[8][TSTRIDE];   // per-transform input/pack buffer
    __shared__ float2 TWH[257];         // e^{+i pi k / 512}, k = 0..256
    __shared__ float2 winSS[512];       // (win[2n], win[2n+1]) / 1024

    const int tid = threadIdx.x;

    if (tid < 257) {
        float s, c;
        __sincosf((FPI / 512.0f) * (float)tid, &s, &c);
        TWH[tid] = make_float2(c, s);
    }
    {
        float2 w = __ldg(&((const float2*)win)[tid]);
        winSS[tid] = make_float2(w.x * (1.0f / 1024.0f), w.y * (1.0f / 1024.0f));
    }

    const int blk  = blockIdx.x;        // 0..4095
    const int b    = blk >> 9;          // batch
    const int tile = blk & 511;         // 8 frames per tile
    const size_t base = (size_t)b * NFREQ * NT + (size_t)tile * 8;

    // Coalesced global load: e -> (tl = e&7, k = e>>3)
    for (int e = tid; e < 8 * NFREQ; e += 512) {
        int tl = e & 7;
        int k  = e >> 3;
        size_t g = base + (size_t)k * NT + tl;
        Sm[tl][k] = make_float2(sr[g], si[g]);
    }
    __syncthreads();

    const int u  = tid & 63;    // thread within transform
    const int tr = tid >> 6;    // transform 0..7
    float2* S = Sm[tr];
    // half2 exchange buffer aliased over the start of Sm (18.6 KB < 37.3 KB).
    // Safe: all float2 reads of Sm complete before the first H write (block
    // __syncthreads between pack-reads and exchange stores).
    __half2* H = (__half2*)(&Sm[0][0]) + tr * HSTRIDE;

    const u64c RR = mk(R2, R2);

    constexpr int BR3[8] = {0, 4, 2, 6, 1, 5, 3, 7};

    // ---- Stage 1: Hermitian pack on the fly + DFT-8 over k2 (stride 64).
    // E = X[kk] + conj(X[512-kk]),  O = (X[kk] - conj(X[512-kk])) e^{i pi kk/512}.
    // Low half (k<=256): Z = E + iO.  High half: Z = conj(E - iO).
    // Im of bins 0 and 512 dropped (c2r semantics): only kk==0 masks imag.
    {
        u64c x[8];
        #pragma unroll
        for (int k2 = 0; k2 < 8; ++k2) {
            int k  = u + 64 * k2;
            int kk = (k <= 256) ? k : 512 - k;
            float ax, ay, bx, by;
            { float2 t = S[kk];        ax = t.x; ay = (kk == 0) ? 0.0f : t.y; }
            { float2 t = S[512 - kk];  bx = t.x; by = (kk == 0) ? 0.0f : -t.y; }
            u64c A  = mk(ax, ay);
            u64c Bc = mk(bx, by);
            u64c E  = f2add(A, Bc);
            u64c P  = muli(cmul(f2sub(A, Bc), *(const u64c*)&TWH[kk]));  // i*O
            x[k2] = (k <= 256) ? f2add(E, P) : cconj(f2sub(E, P));
        }
        idft8(x, RR);
        __syncthreads();                    // ALL transforms' pack reads done
        #pragma unroll
        for (int p = 0; p < 8; ++p) H[9 * u + BR3[p]] = toh2(x[p]);  // A[j][n2]
        __syncthreads();
    }

    // ---- Stage 2: twiddle e^{2 pi i n2 k1/64}; DFT-8 over k1.
    {
        const int n2 = u & 7;
        const int k0 = u >> 3;
        u64c a[8];
        #pragma unroll
        for (int k1 = 0; k1 < 8; ++k1) a[k1] = fromh2(H[9 * (k0 + 8 * k1) + n2]);
        #pragma unroll
        for (int k1 = 1; k1 < 8; ++k1) {
            float s, c;
            __sincosf((2.0f * FPI / 64.0f) * (float)(n2 * k1), &s, &c);
            a[k1] = cmulcs(a[k1], c, s);
        }
        idft8(a, RR);
        __syncthreads();
        #pragma unroll
        for (int p = 0; p < 8; ++p)
            H[9 * (n2 + 8 * BR3[p]) + k0] = toh2(a[p]);   // B[m = n2+8*n1][k0]
        __syncthreads();
    }

    // ---- Stage 3: twiddle e^{2 pi i m k0/512}; DFT-8 over k0; write frames.
    {
        const int m = u;
        u64c c[8];
        #pragma unroll
        for (int k0 = 0; k0 < 8; ++k0) c[k0] = fromh2(H[9 * m + k0]);
        #pragma unroll
        for (int k0 = 1; k0 < 8; ++k0) {
            float s, cc;
            __sincosf((2.0f * FPI / 512.0f) * (float)(m * k0), &s, &cc);
            c[k0] = cmulcs(c[k0], cc, s);
        }
        idft8(c, RR);

        // z[n], n = m + 64*n0. Even/odd unpack: x[2n]=Re, x[2n+1]=Im.
        const int t = tile * 8 + tr;
        __half2* fout = (__half2*)(g_frames + (((size_t)b * NT + t) << 10));
        #pragma unroll
        for (int p = 0; p < 8; ++p) {
            int n = m + 64 * BR3[p];
            u64c wv = *(const u64c*)&winSS[n];   // (w[2n], w[2n+1]) / 1024
            fout[n] = toh2(f2mul(c[p], wv));
        }
    }
}

// ---------------------------------------------------------------------------
// Kernel 2: overlap-add gather + envelope divide + crop.
// 2 samples/thread: half2 frame loads, float2 window/output.
// ---------------------------------------------------------------------------
__global__ __launch_bounds__(256) void istft_ola_kernel(
    const float* __restrict__ win,
    float* __restrict__ out)
{
    int v = blockIdx.x * 256 + threadIdx.x;   // 0 .. OUT_LEN/2 - 1
    int m = v * 2;
    int n = m + PAD;                          // even
    int q = n >> 8;
    int tlo = max(0, q - 3);
    int thi = min(NT - 1, q);

    float2 env = make_float2(0.f, 0.f);
    float2 acc[BATCH];
    #pragma unroll
    for (int b = 0; b < BATCH; ++b) acc[b] = make_float2(0.f, 0.f);

    for (int t = tlo; t <= thi; ++t) {
        int w = n - (t << 8);                 // 0..1022, even
        float2 wv = __ldg((const float2*)(win + w));
        env.x += wv.x * wv.x;
        env.y += wv.y * wv.y;
        #pragma unroll
        for (int b = 0; b < BATCH; ++b) {
            __half2 hv = *(const __half2*)(g_frames + ((((size_t)b * NT + t) << 10) + w));
            float2 f = __half22float2(hv);
            acc[b].x += f.x;
            acc[b].y += f.y;
        }
    }

    float ix = 1.0f / fmaxf(env.x, ENV_EPS);
    float iy = 1.0f / fmaxf(env.y, ENV_EPS);
    #pragma unroll
    for (int b = 0; b < BATCH; ++b) {
        float2 o = make_float2(acc[b].x * ix, acc[b].y * iy);
        *(float2*)(out + (size_t)b * OUT_LEN + m) = o;
    }
}

// ---------------------------------------------------------------------------
extern "C" void kernel_launch(void* const* d_in, const int* in_sizes, int n_in,
                              void* d_out, int out_size)
{
    const float* spec_real = (const float*)d_in[0];
    const float* spec_imag = (const float*)d_in[1];
    const float* window    = (const float*)d_in[2];
    float* out = (float*)d_out;

    istft_fft_kernel<<<BATCH * (NT / 8), 512>>>(spec_real, spec_imag, window);
    istft_ola_kernel<<<OUT_LEN / 2 / 256, 256>>>(window, out);
}

// round 16
// speedup vs baseline: 1.5485x; 1.0231x over previous
#include <cuda_runtime.h>
#include <cuda_bf16.h>
#include <cuda_fp16.h>
#include <math.h>

// Problem constants
#define BATCH   8
#define NFREQ   513          // N_FFT/2 + 1
#define NT      4096         // frames
#define HOP     256
#define WIN     1024
#define PAD     384          // (WIN - HOP)/2
#define OUT_LEN 1048576      // (NT-1)*HOP + WIN - 2*PAD
#define ENV_EPS 1e-11f
#define FPI     3.14159265358979323846f
#define R2      0.70710678118654752f

// Scratch: windowed frames [B][T][WIN] in fp16 (67 MB)
__device__ __half g_frames[(size_t)BATCH * NT * WIN];

// ---------------------------------------------------------------------------
// Packed f32x2 complex arithmetic (AoS: lo = real, hi = imag).
// ---------------------------------------------------------------------------
typedef unsigned long long u64c;

__device__ __forceinline__ u64c mk(float x, float y) {
    u64c r; asm("mov.b64 %0,{%1,%2};" : "=l"(r) : "f"(x), "f"(y)); return r;
}
__device__ __forceinline__ void un(u64c a, float& x, float& y) {
    asm("mov.b64 {%0,%1},%2;" : "=f"(x), "=f"(y) : "l"(a));
}
__device__ __forceinline__ u64c f2add(u64c a, u64c b) {
    u64c r; asm("add.rn.f32x2 %0,%1,%2;" : "=l"(r) : "l"(a), "l"(b)); return r;
}
__device__ __forceinline__ u64c f2sub(u64c a, u64c b) {
    u64c r; asm("sub.rn.f32x2 %0,%1,%2;" : "=l"(r) : "l"(a), "l"(b)); return r;
}
__device__ __forceinline__ u64c f2mul(u64c a, u64c b) {
    u64c r; asm("mul.rn.f32x2 %0,%1,%2;" : "=l"(r) : "l"(a), "l"(b)); return r;
}
__device__ __forceinline__ u64c f2fma(u64c a, u64c b, u64c c) {
    u64c r; asm("fma.rn.f32x2 %0,%1,%2,%3;" : "=l"(r) : "l"(a), "l"(b), "l"(c)); return r;
}
// multiply by i: (x,y) -> (-y, x)
__device__ __forceinline__ u64c muli(u64c a) {
    float x, y; un(a, x, y); return mk(-y, x);
}
// conj: (x,y) -> (x,-y)
__device__ __forceinline__ u64c cconj(u64c a) {
    float x, y; un(a, x, y); return mk(x, -y);
}
// complex multiply: 1 mul + 1 fma on fma pipe
__device__ __forceinline__ u64c cmul(u64c a, u64c b) {
    float bx, by; un(b, bx, by);
    float ax, ay; un(a, ax, ay);
    u64c t = f2mul(mk(-ay, ax), mk(by, by));   // (-ay*by, ax*by)
    return f2fma(a, mk(bx, bx), t);            // (ax*bx - ay*by, ay*bx + ax*by)
}
// complex multiply by scalar twiddle (c, s)
__device__ __forceinline__ u64c cmulcs(u64c a, float c, float s) {
    float ax, ay; un(a, ax, ay);
    u64c t = f2mul(mk(-ay, ax), mk(s, s));
    return f2fma(a, mk(c, c), t);
}
// u64c (re,im) -> half2
__device__ __forceinline__ __half2 toh2(u64c a) {
    float x, y; un(a, x, y);
    return __floats2half2_rn(x, y);
}
// half2 -> u64c
__device__ __forceinline__ u64c fromh2(__half2 h) {
    float2 f = __half22float2(h);
    return mk(f.x, f.y);
}

// 8-point DFT with sign +i (inverse), radix-2 DIF, packed registers.
// Output bit-reversed: slot p holds output index brev3(p) = {0,4,2,6,1,5,3,7}[p].
__device__ __forceinline__ void idft8(u64c x[8], u64c rr)
{
    u64c u, v, d;
    // stage h=4, twiddles 1, (R2+iR2), i, (-R2+iR2)
    u = x[0]; v = x[4];
    x[0] = f2add(u, v);
    x[4] = f2sub(u, v);
    u = x[1]; v = x[5]; d = f2sub(u, v);
    x[1] = f2add(u, v);
    x[5] = f2mul(f2add(d, muli(d)), rr);            // (R2(dx-dy), R2(dx+dy))
    u = x[2]; v = x[6]; d = f2sub(u, v);
    x[2] = f2add(u, v);
    x[6] = muli(d);
    u = x[3]; v = x[7]; d = f2sub(u, v);
    x[3] = f2add(u, v);
    x[7] = f2mul(f2sub(muli(d), d), rr);            // (-R2(dx+dy), R2(dx-dy))
    // stage h=2, twiddles 1, i
    #pragma unroll
    for (int g = 0; g < 8; g += 4) {
        u = x[g]; v = x[g + 2];
        x[g]     = f2add(u, v);
        x[g + 2] = f2sub(u, v);
        u = x[g + 1]; v = x[g + 3]; d = f2sub(u, v);
        x[g + 1] = f2add(u, v);
        x[g + 3] = muli(d);
    }
    // stage h=1
    #pragma unroll
    for (int g = 0; g < 8; g += 2) {
        u = x[g]; v = x[g + 1];
        x[g]     = f2add(u, v);
        x[g + 1] = f2sub(u, v);
    }
}

// ---------------------------------------------------------------------------
// Kernel 1: fused Hermitian pack + 512-pt inverse FFT (3 x radix-8 Stockham,
// 64 threads/transform, 8 transforms per 512-thread block), window + scale,
// fp16 frame output. ALL smem data paths in half2 (input, exchanges, window);
// only the Hermitian twiddle table stays fp32.
// ---------------------------------------------------------------------------
#define ISTRIDE 516   // half2 stride per transform, input buffer (516%32==4 -> CF)
#define HSTRIDE 583   // half2 stride per transform, exchange buffer

__global__ void __launch_bounds__(512) istft_fft_kernel(
    const float* __restrict__ sr,   // (B, 513, 4096)
    const float* __restrict__ si,
    const float* __restrict__ win)  // (1024,)
{
    __shared__ __half2 IN[8][ISTRIDE];  // packed (re,im) input spectrum
    __shared__ __half2 H[8][HSTRIDE];   // inter-stage exchange buffer
    __shared__ float2  TWH[257];        // e^{+i pi k / 512}, k = 0..256 (fp32)
    __shared__ __half2 winH[512];       // (win[2n], win[2n+1]) / 1024

    const int tid = threadIdx.x;

    if (tid < 257) {
        float s, c;
        __sincosf((FPI / 512.0f) * (float)tid, &s, &c);
        TWH[tid] = make_float2(c, s);
    }
    {
        float2 w = __ldg(&((const float2*)win)[tid]);
        winH[tid] = __floats2half2_rn(w.x * (1.0f / 1024.0f), w.y * (1.0f / 1024.0f));
    }

    const int blk  = blockIdx.x;        // 0..4095
    const int b    = blk >> 9;          // batch
    const int tile = blk & 511;         // 8 frames per tile
    const size_t base = (size_t)b * NFREQ * NT + (size_t)tile * 8;

    // Coalesced global load: e -> (tl = e&7, k = e>>3); store packed fp16.
    for (int e = tid; e < 8 * NFREQ; e += 512) {
        int tl = e & 7;
        int k  = e >> 3;
        size_t g = base + (size_t)k * NT + tl;
        IN[tl][k] = __floats2half2_rn(sr[g], si[g]);
    }
    __syncthreads();

    const int u  = tid & 63;    // thread within transform
    const int tr = tid >> 6;    // transform 0..7
    const __half2* Si = IN[tr];
    __half2* Hx = H[tr];

    const u64c RR = mk(R2, R2);

    constexpr int BR3[8] = {0, 4, 2, 6, 1, 5, 3, 7};

    // ---- Stage 1: Hermitian pack on the fly + DFT-8 over k2 (stride 64).
    // E = X[kk] + conj(X[512-kk]),  O = (X[kk] - conj(X[512-kk])) e^{i pi kk/512}.
    // Low half (k<=256): Z = E + iO.  High half: Z = conj(E - iO).
    // Im of bins 0 and 512 dropped (c2r semantics): only kk==0 masks imag.
    {
        u64c x[8];
        #pragma unroll
        for (int k2 = 0; k2 < 8; ++k2) {
            int k  = u + 64 * k2;
            int kk = (k <= 256) ? k : 512 - k;
            float2 fa = __half22float2(Si[kk]);
            float2 fb = __half22float2(Si[512 - kk]);
            float ay = (kk == 0) ? 0.0f : fa.y;
            float by = (kk == 0) ? 0.0f : -fb.y;
            u64c A  = mk(fa.x, ay);
            u64c Bc = mk(fb.x, by);
            u64c E  = f2add(A, Bc);
            u64c P  = muli(cmul(f2sub(A, Bc), *(const u64c*)&TWH[kk]));  // i*O
            x[k2] = (k <= 256) ? f2add(E, P) : cconj(f2sub(E, P));
        }
        idft8(x, RR);
        // No cross-buffer hazard (IN and H are separate); sync only to order
        // this stage's H writes against stage-2 reads.
        #pragma unroll
        for (int p = 0; p < 8; ++p) Hx[9 * u + BR3[p]] = toh2(x[p]);  // A[j][n2]
        __syncthreads();
    }

    // ---- Stage 2: twiddle e^{2 pi i n2 k1/64}; DFT-8 over k1.
    {
        const int n2 = u & 7;
        const int k0 = u >> 3;
        u64c a[8];
        #pragma unroll
        for (int k1 = 0; k1 < 8; ++k1) a[k1] = fromh2(Hx[9 * (k0 + 8 * k1) + n2]);
        #pragma unroll
        for (int k1 = 1; k1 < 8; ++k1) {
            float s, c;
            __sincosf((2.0f * FPI / 64.0f) * (float)(n2 * k1), &s, &c);
            a[k1] = cmulcs(a[k1], c, s);
        }
        idft8(a, RR);
        __syncthreads();
        #pragma unroll
        for (int p = 0; p < 8; ++p)
            Hx[9 * (n2 + 8 * BR3[p]) + k0] = toh2(a[p]);   // B[m = n2+8*n1][k0]
        __syncthreads();
    }

    // ---- Stage 3: twiddle e^{2 pi i m k0/512}; DFT-8 over k0; write frames.
    {
        const int m = u;
        u64c c[8];
        #pragma unroll
        for (int k0 = 0; k0 < 8; ++k0) c[k0] = fromh2(Hx[9 * m + k0]);
        #pragma unroll
        for (int k0 = 1; k0 < 8; ++k0) {
            float s, cc;
            __sincosf((2.0f * FPI / 512.0f) * (float)(m * k0), &s, &cc);
            c[k0] = cmulcs(c[k0], cc, s);
        }
        idft8(c, RR);

        // z[n], n = m + 64*n0. Even/odd unpack: x[2n]=Re, x[2n+1]=Im.
        const int t = tile * 8 + tr;
        __half2* fout = (__half2*)(g_frames + (((size_t)b * NT + t) << 10));
        #pragma unroll
        for (int p = 0; p < 8; ++p) {
            int n = m + 64 * BR3[p];
            float2 wv = __half22float2(winH[n]);   // (w[2n], w[2n+1]) / 1024
            fout[n] = toh2(f2mul(c[p], mk(wv.x, wv.y)));
        }
    }
}

// ---------------------------------------------------------------------------
// Kernel 2: overlap-add gather + envelope divide + crop.
// 2 samples/thread: half2 frame loads, float2 window/output.
// ---------------------------------------------------------------------------
__global__ __launch_bounds__(256) void istft_ola_kernel(
    const float* __restrict__ win,
    float* __restrict__ out)
{
    int v = blockIdx.x * 256 + threadIdx.x;   // 0 .. OUT_LEN/2 - 1
    int m = v * 2;
    int n = m + PAD;                          // even
    int q = n >> 8;
    int tlo = max(0, q - 3);
    int thi = min(NT - 1, q);

    float2 env = make_float2(0.f, 0.f);
    float2 acc[BATCH];
    #pragma unroll
    for (int b = 0; b < BATCH; ++b) acc[b] = make_float2(0.f, 0.f);

    for (int t = tlo; t <= thi; ++t) {
        int w = n - (t << 8);                 // 0..1022, even
        float2 wv = __ldg((const float2*)(win + w));
        env.x += wv.x * wv.x;
        env.y += wv.y * wv.y;
        #pragma unroll
        for (int b = 0; b < BATCH; ++b) {
            __half2 hv = *(const __half2*)(g_frames + ((((size_t)b * NT + t) << 10) + w));
            float2 f = __half22float2(hv);
            acc[b].x += f.x;
            acc[b].y += f.y;
        }
    }

    float ix = 1.0f / fmaxf(env.x, ENV_EPS);
    float iy = 1.0f / fmaxf(env.y, ENV_EPS);
    #pragma unroll
    for (int b = 0; b < BATCH; ++b) {
        float2 o = make_float2(acc[b].x * ix, acc[b].y * iy);
        *(float2*)(out + (size_t)b * OUT_LEN + m) = o;
    }
}

// ---------------------------------------------------------------------------
extern "C" void kernel_launch(void* const* d_in, const int* in_sizes, int n_in,
                              void* d_out, int out_size)
{
    const float* spec_real = (const float*)d_in[0];
    const float* spec_imag = (const float*)d_in[1];
    const float* window    = (const float*)d_in[2];
    float* out = (float*)d_out;

    istft_fft_kernel<<<BATCH * (NT / 8), 512>>>(spec_real, spec_imag, window);
    istft_ola_kernel<<<OUT_LEN / 2 / 256, 256>>>(window, out);
}